// round 1
// baseline (speedup 1.0000x reference)
#include <cuda_runtime.h>
#include <cstdint>

// Problem-fixed sizes (from setup_inputs): N=100000, E=3200000, F_in=128, H=16.
#define MAXN 100000
#define MAXE 3200000

// Scratch (device globals -- no allocation allowed).
__device__ float g_deg[MAXN];                         // deg, then dinv in place
__device__ __align__(16) float g_pre[MAXN * 16];      // pre = h0*dinv, later u
__device__ __align__(16) float g_acc[MAXN * 16];      // layer1 accumulator, later v
__device__ __align__(16) float g_pg[MAXN * 2];        // pg = (h@W2)*dinv
__device__ __align__(16) float g_acc2[MAXN * 2];      // layer2 accumulator
__device__ int g_is64;

// ---------------------------------------------------------------------------
// init: zero accumulators, deg=1 (self loop), detect int32 vs int64 edges
// ---------------------------------------------------------------------------
__global__ void __launch_bounds__(256) init_kernel(const void* __restrict__ edges,
                                                   long long E, int N) {
    long long j = (long long)blockIdx.x * blockDim.x + threadIdx.x;

    if (blockIdx.x == 0 && threadIdx.x < 32) {
        // One warp checks 512 uint64 words. If data is int64 (values < N),
        // every word < N. If int32, the upper 32 bits are a random index,
        // so almost every word >= 2^32.
        const unsigned long long* p = (const unsigned long long*)edges;
        bool ok = true;
        #pragma unroll
        for (int k = 0; k < 16; k++) {
            long long idx = (long long)threadIdx.x * 16 + k;
            if (idx < E) {
                unsigned long long v = p[idx];
                if (v >= (unsigned long long)N) ok = false;
            }
        }
        unsigned mask = __ballot_sync(0xffffffffu, ok);
        if (threadIdx.x == 0) g_is64 = (mask == 0xffffffffu) ? 1 : 0;
    }

    if (j < (long long)N * 16) g_acc[j] = 0.0f;
    if (j < (long long)N * 2)  g_acc2[j] = 0.0f;
    if (j < N)                 g_deg[j] = 1.0f;   // self loop
}

// ---------------------------------------------------------------------------
// degree: deg[t] += 1 for every edge target
// ---------------------------------------------------------------------------
__global__ void __launch_bounds__(256) deg_kernel(const void* __restrict__ edges,
                                                  long long E) {
    long long e = (long long)blockIdx.x * blockDim.x + threadIdx.x;
    if (e >= E) return;
    int t;
    if (g_is64) t = (int)((const long long*)edges)[E + e];
    else        t = ((const int*)edges)[E + e];
    atomicAdd(&g_deg[t], 1.0f);
}

// ---------------------------------------------------------------------------
// dinv = rsqrt(deg)
// ---------------------------------------------------------------------------
__global__ void __launch_bounds__(256) dinv_kernel(int N) {
    int i = blockIdx.x * blockDim.x + threadIdx.x;
    if (i < N) g_deg[i] = rsqrtf(g_deg[i]);
}

// ---------------------------------------------------------------------------
// pre[i] = (x[i] @ W1) * dinv[i]     (W1: [128,16] row-major, in shared)
// ---------------------------------------------------------------------------
__global__ void __launch_bounds__(256) h0pre_kernel(const float* __restrict__ x,
                                                    const float* __restrict__ W1,
                                                    int N) {
    __shared__ float sW[2048];  // 128*16
    for (int k = threadIdx.x; k < 2048; k += blockDim.x) sW[k] = W1[k];
    __syncthreads();

    int i = blockIdx.x * blockDim.x + threadIdx.x;
    if (i >= N) return;

    float a[16];
    #pragma unroll
    for (int j = 0; j < 16; j++) a[j] = 0.0f;

    const float4* xr = (const float4*)(x + (size_t)i * 128);
    #pragma unroll 4
    for (int k = 0; k < 32; k++) {
        float4 xv = xr[k];
        const float* w = &sW[k * 64];
        #pragma unroll
        for (int j = 0; j < 16; j++) a[j] = fmaf(xv.x, w[j],      a[j]);
        #pragma unroll
        for (int j = 0; j < 16; j++) a[j] = fmaf(xv.y, w[16 + j], a[j]);
        #pragma unroll
        for (int j = 0; j < 16; j++) a[j] = fmaf(xv.z, w[32 + j], a[j]);
        #pragma unroll
        for (int j = 0; j < 16; j++) a[j] = fmaf(xv.w, w[48 + j], a[j]);
    }

    float di = g_deg[i];
    float4* o = (float4*)(g_pre + (size_t)i * 16);
    #pragma unroll
    for (int q = 0; q < 4; q++)
        o[q] = make_float4(a[q*4]*di, a[q*4+1]*di, a[q*4+2]*di, a[q*4+3]*di);
}

// ---------------------------------------------------------------------------
// scatter layer 1: acc[t] += pre[s]   (16 floats, 4x red.v4)
// ---------------------------------------------------------------------------
__global__ void __launch_bounds__(256) scatter1_kernel(const void* __restrict__ edges,
                                                       long long E) {
    long long e = (long long)blockIdx.x * blockDim.x + threadIdx.x;
    if (e >= E) return;
    int s, t;
    if (g_is64) {
        const long long* p = (const long long*)edges;
        s = (int)p[e]; t = (int)p[E + e];
    } else {
        const int* p = (const int*)edges;
        s = p[e]; t = p[E + e];
    }
    const float4* sp = (const float4*)(g_pre + (size_t)s * 16);
    float* dst = g_acc + (size_t)t * 16;
    #pragma unroll
    for (int q = 0; q < 4; q++) {
        float4 v = sp[q];
        asm volatile(
            "{ .reg .u64 a; cvta.to.global.u64 a, %0; "
            "red.global.add.v4.f32 [a], {%1, %2, %3, %4}; }"
            :: "l"(dst + q * 4), "f"(v.x), "f"(v.y), "f"(v.z), "f"(v.w)
            : "memory");
    }
}

// ---------------------------------------------------------------------------
// finalize layer 1 + precompute edge-MLP node terms:
//   h    = relu(dinv*(acc + pre) + b1)
//   u    = h @ We1[0:16]  + be1      -> overwrites g_pre
//   v    = h @ We1[16:32]            -> overwrites g_acc
//   pg   = (h @ W2) * dinv
// ---------------------------------------------------------------------------
__global__ void __launch_bounds__(256) finalize_kernel(const float* __restrict__ b1,
                                                       const float* __restrict__ We1,
                                                       const float* __restrict__ be1,
                                                       const float* __restrict__ W2,
                                                       int N) {
    __shared__ float sWe1[512];  // [32,16]
    __shared__ float sW2[32];    // [16,2]
    __shared__ float sb1[16], sbe1[16];
    for (int k = threadIdx.x; k < 512; k += blockDim.x) sWe1[k] = We1[k];
    if (threadIdx.x < 32) sW2[threadIdx.x] = W2[threadIdx.x];
    if (threadIdx.x < 16) { sb1[threadIdx.x] = b1[threadIdx.x]; sbe1[threadIdx.x] = be1[threadIdx.x]; }
    __syncthreads();

    int i = blockIdx.x * blockDim.x + threadIdx.x;
    if (i >= N) return;

    float di = g_deg[i];
    float h[16];
    const float4* ap = (const float4*)(g_acc + (size_t)i * 16);
    const float4* pp = (const float4*)(g_pre + (size_t)i * 16);
    #pragma unroll
    for (int q = 0; q < 4; q++) {
        float4 av = ap[q], pv = pp[q];
        h[q*4+0] = fmaxf(di * (av.x + pv.x) + sb1[q*4+0], 0.0f);
        h[q*4+1] = fmaxf(di * (av.y + pv.y) + sb1[q*4+1], 0.0f);
        h[q*4+2] = fmaxf(di * (av.z + pv.z) + sb1[q*4+2], 0.0f);
        h[q*4+3] = fmaxf(di * (av.w + pv.w) + sb1[q*4+3], 0.0f);
    }

    float u[16], v[16];
    #pragma unroll
    for (int j = 0; j < 16; j++) { u[j] = sbe1[j]; v[j] = 0.0f; }
    #pragma unroll
    for (int k = 0; k < 16; k++) {
        float hk = h[k];
        const float* wu = &sWe1[k * 16];
        const float* wv = &sWe1[(16 + k) * 16];
        #pragma unroll
        for (int j = 0; j < 16; j++) u[j] = fmaf(hk, wu[j], u[j]);
        #pragma unroll
        for (int j = 0; j < 16; j++) v[j] = fmaf(hk, wv[j], v[j]);
    }
    float p0 = 0.0f, p1 = 0.0f;
    #pragma unroll
    for (int k = 0; k < 16; k++) {
        p0 = fmaf(h[k], sW2[k * 2],     p0);
        p1 = fmaf(h[k], sW2[k * 2 + 1], p1);
    }

    float4* uo = (float4*)(g_pre + (size_t)i * 16);
    float4* vo = (float4*)(g_acc + (size_t)i * 16);
    #pragma unroll
    for (int q = 0; q < 4; q++) {
        uo[q] = make_float4(u[q*4], u[q*4+1], u[q*4+2], u[q*4+3]);
        vo[q] = make_float4(v[q*4], v[q*4+1], v[q*4+2], v[q*4+3]);
    }
    float2* po = (float2*)(g_pg + (size_t)i * 2);
    *po = make_float2(p0 * di, p1 * di);
}

// ---------------------------------------------------------------------------
// edge kernel: edge_out[e] = sigmoid(relu(u[s]+v[t]) . We2 + be2)
//              acc2[t] += pg[s]   (layer-2 scatter, red.v2)
// ---------------------------------------------------------------------------
__global__ void __launch_bounds__(256) edge_kernel(const void* __restrict__ edges,
                                                   long long E,
                                                   const float* __restrict__ We2,
                                                   const float* __restrict__ be2,
                                                   float* __restrict__ edge_out) {
    __shared__ float sWe2[16];
    __shared__ float sbe2;
    if (threadIdx.x < 16) sWe2[threadIdx.x] = We2[threadIdx.x];
    if (threadIdx.x == 0) sbe2 = be2[0];
    __syncthreads();

    long long e = (long long)blockIdx.x * blockDim.x + threadIdx.x;
    if (e >= E) return;
    int s, t;
    if (g_is64) {
        const long long* p = (const long long*)edges;
        s = (int)p[e]; t = (int)p[E + e];
    } else {
        const int* p = (const int*)edges;
        s = p[e]; t = p[E + e];
    }

    const float4* up = (const float4*)(g_pre + (size_t)s * 16);
    const float4* vp = (const float4*)(g_acc + (size_t)t * 16);
    float zz = sbe2;
    #pragma unroll
    for (int q = 0; q < 4; q++) {
        float4 uu = up[q], vv = vp[q];
        zz = fmaf(fmaxf(uu.x + vv.x, 0.0f), sWe2[q*4+0], zz);
        zz = fmaf(fmaxf(uu.y + vv.y, 0.0f), sWe2[q*4+1], zz);
        zz = fmaf(fmaxf(uu.z + vv.z, 0.0f), sWe2[q*4+2], zz);
        zz = fmaf(fmaxf(uu.w + vv.w, 0.0f), sWe2[q*4+3], zz);
    }
    edge_out[e] = 1.0f / (1.0f + __expf(-zz));

    float2 pv = *(const float2*)(g_pg + (size_t)s * 2);
    float* dst = g_acc2 + (size_t)t * 2;
    asm volatile(
        "{ .reg .u64 a; cvta.to.global.u64 a, %0; "
        "red.global.add.v2.f32 [a], {%1, %2}; }"
        :: "l"(dst), "f"(pv.x), "f"(pv.y)
        : "memory");
}

// ---------------------------------------------------------------------------
// node epilogue: node_out[i] = dinv[i]*(acc2[i] + pg[i]) + b2
// ---------------------------------------------------------------------------
__global__ void __launch_bounds__(256) node_out_kernel(const float* __restrict__ b2,
                                                       float* __restrict__ node_out,
                                                       int N) {
    int i = blockIdx.x * blockDim.x + threadIdx.x;
    if (i >= N) return;
    float di = g_deg[i];
    float2 a = *(const float2*)(g_acc2 + (size_t)i * 2);
    float2 p = *(const float2*)(g_pg + (size_t)i * 2);
    float b0 = __ldg(&b2[0]), bb1 = __ldg(&b2[1]);
    float2 o = make_float2(di * (a.x + p.x) + b0, di * (a.y + p.y) + bb1);
    *(float2*)(node_out + (size_t)i * 2) = o;
}

// ---------------------------------------------------------------------------
extern "C" void kernel_launch(void* const* d_in, const int* in_sizes, int n_in,
                              void* d_out, int out_size) {
    const float* x     = (const float*)d_in[0];
    const void*  edges = d_in[1];
    const float* W1    = (const float*)d_in[2];
    const float* b1    = (const float*)d_in[3];
    const float* W2    = (const float*)d_in[4];
    const float* b2    = (const float*)d_in[5];
    const float* We1   = (const float*)d_in[6];
    const float* be1   = (const float*)d_in[7];
    const float* We2   = (const float*)d_in[8];
    const float* be2   = (const float*)d_in[9];

    int N = in_sizes[0] / 128;
    long long E = (long long)in_sizes[1] / 2;

    float* out      = (float*)d_out;
    float* node_out = out;                       // [N,2]
    float* edge_out = out + (size_t)2 * N;       // [E]

    const int B = 256;
    int gN   = (N + B - 1) / B;
    int gN16 = (int)(((long long)N * 16 + B - 1) / B);
    int gE   = (int)((E + B - 1) / B);

    init_kernel<<<gN16, B>>>(edges, E, N);
    deg_kernel<<<gE, B>>>(edges, E);
    dinv_kernel<<<gN, B>>>(N);
    h0pre_kernel<<<gN, B>>>(x, W1, N);
    scatter1_kernel<<<gE, B>>>(edges, E);
    finalize_kernel<<<gN, B>>>(b1, We1, be1, W2, N);
    edge_kernel<<<gE, B>>>(edges, E, We2, be2, edge_out);
    node_out_kernel<<<gN, B>>>(b2, node_out, N);
}

// round 2
// speedup vs baseline: 1.2010x; 1.2010x over previous
#include <cuda_runtime.h>
#include <cuda_fp16.h>
#include <cstdint>

// Problem-fixed sizes (from setup_inputs): N=100000, E=3200000, F_in=128, H=16.
#define MAXN 100000
#define MAXE 3200000

// Scratch (device globals -- no allocation allowed).
__device__ float g_deg[MAXN];                          // deg, then dinv in place
__device__ __align__(16) float g_pre[MAXN * 16];       // pre = h0*dinv
__device__ __align__(16) float g_acc[MAXN * 16];       // layer1 accumulator
__device__ __align__(16) float g_pg[MAXN * 2];         // pg = (h@W2)*dinv
__device__ __align__(16) float g_acc2[MAXN * 2];       // layer2 accumulator
__device__ __align__(16) int2 g_ep[MAXE];              // converted int32 (s,t) pairs
__device__ __align__(16) __half2 g_uh[MAXN * 8];       // u (fp16) for edge MLP
__device__ __align__(16) __half2 g_vh[MAXN * 8];       // v (fp16) for edge MLP
__device__ int g_is64;

// ---------------------------------------------------------------------------
// init: zero accumulators, deg=1 (self loop), detect int32 vs int64 edges
// ---------------------------------------------------------------------------
__global__ void __launch_bounds__(256) init_kernel(const void* __restrict__ edges,
                                                   long long E, int N) {
    long long j = (long long)blockIdx.x * blockDim.x + threadIdx.x;

    if (blockIdx.x == 0 && threadIdx.x < 32) {
        // One warp checks 512 uint64 words. If data is int64 (values < N),
        // every word < N. If int32, the upper 32 bits hold a random index,
        // so almost every word >= 2^32.
        const unsigned long long* p = (const unsigned long long*)edges;
        bool ok = true;
        #pragma unroll
        for (int k = 0; k < 16; k++) {
            long long idx = (long long)threadIdx.x * 16 + k;
            if (idx < E) {
                unsigned long long v = p[idx];
                if (v >= (unsigned long long)N) ok = false;
            }
        }
        unsigned mask = __ballot_sync(0xffffffffu, ok);
        if (threadIdx.x == 0) g_is64 = (mask == 0xffffffffu) ? 1 : 0;
    }

    if (j < (long long)N * 16) g_acc[j] = 0.0f;
    if (j < (long long)N * 2)  g_acc2[j] = 0.0f;
    if (j < N)                 g_deg[j] = 1.0f;   // self loop
}

// ---------------------------------------------------------------------------
// convert + degree: g_ep[e] = (s,t) as int32; deg[t] += 1
// ---------------------------------------------------------------------------
__global__ void __launch_bounds__(256) convdeg_kernel(const void* __restrict__ edges,
                                                      long long E) {
    long long e = (long long)blockIdx.x * blockDim.x + threadIdx.x;
    if (e >= E) return;
    int s, t;
    if (g_is64) {
        const long long* p = (const long long*)edges;
        s = (int)p[e]; t = (int)p[E + e];
    } else {
        const int* p = (const int*)edges;
        s = p[e]; t = p[E + e];
    }
    g_ep[e] = make_int2(s, t);
    atomicAdd(&g_deg[t], 1.0f);
}

// ---------------------------------------------------------------------------
// dinv = rsqrt(deg)
// ---------------------------------------------------------------------------
__global__ void __launch_bounds__(256) dinv_kernel(int N) {
    int i = blockIdx.x * blockDim.x + threadIdx.x;
    if (i < N) g_deg[i] = rsqrtf(g_deg[i]);
}

// ---------------------------------------------------------------------------
// pre[i] = (x[i] @ W1) * dinv[i]   (W1: [128,16] row-major, in shared, LDS.128)
// ---------------------------------------------------------------------------
__global__ void __launch_bounds__(256) h0pre_kernel(const float* __restrict__ x,
                                                    const float* __restrict__ W1,
                                                    int N) {
    __shared__ __align__(16) float sW[2048];  // 128*16
    for (int k = threadIdx.x; k < 512; k += blockDim.x)
        ((float4*)sW)[k] = ((const float4*)W1)[k];
    __syncthreads();

    int i = blockIdx.x * blockDim.x + threadIdx.x;
    if (i >= N) return;

    float a[16];
    #pragma unroll
    for (int j = 0; j < 16; j++) a[j] = 0.0f;

    const float4* xr = (const float4*)(x + (size_t)i * 128);
    #pragma unroll 4
    for (int k = 0; k < 32; k++) {
        float4 xv = xr[k];
        const float4* w = (const float4*)&sW[k * 64];  // 16 float4 = 4 weight rows
        #pragma unroll
        for (int q = 0; q < 4; q++) {
            float4 w0 = w[q], w1 = w[4 + q], w2 = w[8 + q], w3 = w[12 + q];
            a[q*4+0] = fmaf(xv.x, w0.x, fmaf(xv.y, w1.x, fmaf(xv.z, w2.x, fmaf(xv.w, w3.x, a[q*4+0]))));
            a[q*4+1] = fmaf(xv.x, w0.y, fmaf(xv.y, w1.y, fmaf(xv.z, w2.y, fmaf(xv.w, w3.y, a[q*4+1]))));
            a[q*4+2] = fmaf(xv.x, w0.z, fmaf(xv.y, w1.z, fmaf(xv.z, w2.z, fmaf(xv.w, w3.z, a[q*4+2]))));
            a[q*4+3] = fmaf(xv.x, w0.w, fmaf(xv.y, w1.w, fmaf(xv.z, w2.w, fmaf(xv.w, w3.w, a[q*4+3]))));
        }
    }

    float di = g_deg[i];
    float4* o = (float4*)(g_pre + (size_t)i * 16);
    #pragma unroll
    for (int q = 0; q < 4; q++)
        o[q] = make_float4(a[q*4]*di, a[q*4+1]*di, a[q*4+2]*di, a[q*4+3]*di);
}

// ---------------------------------------------------------------------------
// scatter layer 1: acc[t] += pre[s]   (16 floats, 4x red.v4)
// ---------------------------------------------------------------------------
__global__ void __launch_bounds__(256) scatter1_kernel(long long E) {
    long long e = (long long)blockIdx.x * blockDim.x + threadIdx.x;
    if (e >= E) return;
    int2 st = g_ep[e];
    const float4* sp = (const float4*)(g_pre + (size_t)st.x * 16);
    float* dst = g_acc + (size_t)st.y * 16;
    float4 v0 = sp[0], v1 = sp[1], v2 = sp[2], v3 = sp[3];
    asm volatile(
        "{ .reg .u64 a; cvta.to.global.u64 a, %0; "
        "red.global.add.v4.f32 [a], {%1, %2, %3, %4}; }"
        :: "l"(dst), "f"(v0.x), "f"(v0.y), "f"(v0.z), "f"(v0.w) : "memory");
    asm volatile(
        "{ .reg .u64 a; cvta.to.global.u64 a, %0; "
        "red.global.add.v4.f32 [a], {%1, %2, %3, %4}; }"
        :: "l"(dst + 4), "f"(v1.x), "f"(v1.y), "f"(v1.z), "f"(v1.w) : "memory");
    asm volatile(
        "{ .reg .u64 a; cvta.to.global.u64 a, %0; "
        "red.global.add.v4.f32 [a], {%1, %2, %3, %4}; }"
        :: "l"(dst + 8), "f"(v2.x), "f"(v2.y), "f"(v2.z), "f"(v2.w) : "memory");
    asm volatile(
        "{ .reg .u64 a; cvta.to.global.u64 a, %0; "
        "red.global.add.v4.f32 [a], {%1, %2, %3, %4}; }"
        :: "l"(dst + 12), "f"(v3.x), "f"(v3.y), "f"(v3.z), "f"(v3.w) : "memory");
}

// ---------------------------------------------------------------------------
// finalize layer 1 + precompute edge-MLP node terms:
//   h  = relu(dinv*(acc + pre) + b1)
//   u  = h @ We1[0:16] + be1   -> g_uh (fp16)
//   v  = h @ We1[16:32]        -> g_vh (fp16)
//   pg = (h @ W2) * dinv       -> g_pg (fp32)
// ---------------------------------------------------------------------------
__global__ void __launch_bounds__(256) finalize_kernel(const float* __restrict__ b1,
                                                       const float* __restrict__ We1,
                                                       const float* __restrict__ be1,
                                                       const float* __restrict__ W2,
                                                       int N) {
    __shared__ float sWe1[512];  // [32,16]
    __shared__ float sW2[32];    // [16,2]
    __shared__ float sb1[16], sbe1[16];
    for (int k = threadIdx.x; k < 512; k += blockDim.x) sWe1[k] = We1[k];
    if (threadIdx.x < 32) sW2[threadIdx.x] = W2[threadIdx.x];
    if (threadIdx.x < 16) { sb1[threadIdx.x] = b1[threadIdx.x]; sbe1[threadIdx.x] = be1[threadIdx.x]; }
    __syncthreads();

    int i = blockIdx.x * blockDim.x + threadIdx.x;
    if (i >= N) return;

    float di = g_deg[i];
    float h[16];
    const float4* ap = (const float4*)(g_acc + (size_t)i * 16);
    const float4* pp = (const float4*)(g_pre + (size_t)i * 16);
    #pragma unroll
    for (int q = 0; q < 4; q++) {
        float4 av = ap[q], pv = pp[q];
        h[q*4+0] = fmaxf(di * (av.x + pv.x) + sb1[q*4+0], 0.0f);
        h[q*4+1] = fmaxf(di * (av.y + pv.y) + sb1[q*4+1], 0.0f);
        h[q*4+2] = fmaxf(di * (av.z + pv.z) + sb1[q*4+2], 0.0f);
        h[q*4+3] = fmaxf(di * (av.w + pv.w) + sb1[q*4+3], 0.0f);
    }

    float u[16], v[16];
    #pragma unroll
    for (int j = 0; j < 16; j++) { u[j] = sbe1[j]; v[j] = 0.0f; }
    #pragma unroll
    for (int k = 0; k < 16; k++) {
        float hk = h[k];
        const float* wu = &sWe1[k * 16];
        const float* wv = &sWe1[(16 + k) * 16];
        #pragma unroll
        for (int j = 0; j < 16; j++) u[j] = fmaf(hk, wu[j], u[j]);
        #pragma unroll
        for (int j = 0; j < 16; j++) v[j] = fmaf(hk, wv[j], v[j]);
    }
    float p0 = 0.0f, p1 = 0.0f;
    #pragma unroll
    for (int k = 0; k < 16; k++) {
        p0 = fmaf(h[k], sW2[k * 2],     p0);
        p1 = fmaf(h[k], sW2[k * 2 + 1], p1);
    }

    __half2* uo = g_uh + (size_t)i * 8;
    __half2* vo = g_vh + (size_t)i * 8;
    #pragma unroll
    for (int q = 0; q < 8; q++) {
        uo[q] = __floats2half2_rn(u[q*2], u[q*2+1]);
        vo[q] = __floats2half2_rn(v[q*2], v[q*2+1]);
    }
    float2* po = (float2*)(g_pg + (size_t)i * 2);
    *po = make_float2(p0 * di, p1 * di);
}

// ---------------------------------------------------------------------------
// edge kernel: edge_out[e] = sigmoid(relu(u[s]+v[t]) . We2 + be2)
//              acc2[t] += pg[s]   (layer-2 scatter, red.v2)
// ---------------------------------------------------------------------------
__global__ void __launch_bounds__(256) edge_kernel(long long E,
                                                   const float* __restrict__ We2,
                                                   const float* __restrict__ be2,
                                                   float* __restrict__ edge_out) {
    __shared__ float sWe2[16];
    __shared__ float sbe2;
    if (threadIdx.x < 16) sWe2[threadIdx.x] = We2[threadIdx.x];
    if (threadIdx.x == 0) sbe2 = be2[0];
    __syncthreads();

    long long e = (long long)blockIdx.x * blockDim.x + threadIdx.x;
    if (e >= E) return;
    int2 st = g_ep[e];

    const int4* up = (const int4*)(g_uh + (size_t)st.x * 8);  // 2x16B
    const int4* vp = (const int4*)(g_vh + (size_t)st.y * 8);
    int4 ua = up[0], ub = up[1];
    int4 va = vp[0], vb = vp[1];

    float zz = sbe2;
    const __half2* uh = (const __half2*)&ua;
    const __half2* vh = (const __half2*)&va;
    #pragma unroll
    for (int q = 0; q < 4; q++) {
        float2 uu = __half22float2(uh[q]);
        float2 vv = __half22float2(vh[q]);
        zz = fmaf(fmaxf(uu.x + vv.x, 0.0f), sWe2[q*2+0], zz);
        zz = fmaf(fmaxf(uu.y + vv.y, 0.0f), sWe2[q*2+1], zz);
    }
    const __half2* uh2 = (const __half2*)&ub;
    const __half2* vh2 = (const __half2*)&vb;
    #pragma unroll
    for (int q = 0; q < 4; q++) {
        float2 uu = __half22float2(uh2[q]);
        float2 vv = __half22float2(vh2[q]);
        zz = fmaf(fmaxf(uu.x + vv.x, 0.0f), sWe2[8+q*2+0], zz);
        zz = fmaf(fmaxf(uu.y + vv.y, 0.0f), sWe2[8+q*2+1], zz);
    }
    edge_out[e] = 1.0f / (1.0f + __expf(-zz));

    float2 pv = *(const float2*)(g_pg + (size_t)st.x * 2);
    float* dst = g_acc2 + (size_t)st.y * 2;
    asm volatile(
        "{ .reg .u64 a; cvta.to.global.u64 a, %0; "
        "red.global.add.v2.f32 [a], {%1, %2}; }"
        :: "l"(dst), "f"(pv.x), "f"(pv.y) : "memory");
}

// ---------------------------------------------------------------------------
// node epilogue: node_out[i] = dinv[i]*(acc2[i] + pg[i]) + b2
// ---------------------------------------------------------------------------
__global__ void __launch_bounds__(256) node_out_kernel(const float* __restrict__ b2,
                                                       float* __restrict__ node_out,
                                                       int N) {
    int i = blockIdx.x * blockDim.x + threadIdx.x;
    if (i >= N) return;
    float di = g_deg[i];
    float2 a = *(const float2*)(g_acc2 + (size_t)i * 2);
    float2 p = *(const float2*)(g_pg + (size_t)i * 2);
    float b0 = __ldg(&b2[0]), bb1 = __ldg(&b2[1]);
    float2 o = make_float2(di * (a.x + p.x) + b0, di * (a.y + p.y) + bb1);
    *(float2*)(node_out + (size_t)i * 2) = o;
}

// ---------------------------------------------------------------------------
extern "C" void kernel_launch(void* const* d_in, const int* in_sizes, int n_in,
                              void* d_out, int out_size) {
    const float* x     = (const float*)d_in[0];
    const void*  edges = d_in[1];
    const float* W1    = (const float*)d_in[2];
    const float* b1    = (const float*)d_in[3];
    const float* W2    = (const float*)d_in[4];
    const float* b2    = (const float*)d_in[5];
    const float* We1   = (const float*)d_in[6];
    const float* be1   = (const float*)d_in[7];
    const float* We2   = (const float*)d_in[8];
    const float* be2   = (const float*)d_in[9];

    int N = in_sizes[0] / 128;
    long long E = (long long)in_sizes[1] / 2;

    float* out      = (float*)d_out;
    float* node_out = out;                       // [N,2]
    float* edge_out = out + (size_t)2 * N;       // [E]

    const int B = 256;
    int gN   = (N + B - 1) / B;
    int gN16 = (int)(((long long)N * 16 + B - 1) / B);
    int gE   = (int)((E + B - 1) / B);

    init_kernel<<<gN16, B>>>(edges, E, N);
    convdeg_kernel<<<gE, B>>>(edges, E);
    dinv_kernel<<<gN, B>>>(N);
    h0pre_kernel<<<gN, B>>>(x, W1, N);
    scatter1_kernel<<<gE, B>>>(E);
    finalize_kernel<<<gN, B>>>(b1, We1, be1, W2, N);
    edge_kernel<<<gE, B>>>(E, We2, be2, edge_out);
    node_out_kernel<<<gN, B>>>(b2, node_out, N);
}